// round 4
// baseline (speedup 1.0000x reference)
#include <cuda_runtime.h>

#define NB 4
#define NC 64
#define HW 40
#define KS 11
#define HP 30
#define PIX 1600          // 40*40
#define PW  112           // padded im2 row width in smem
#define POFF 32           // left pad
#define NDX 16            // dx shifts per block
#define OUTN (NB*HP*HP)

__device__ unsigned g_enc[OUTN];
__device__ float    g_inv[OUTN];

__device__ __forceinline__ unsigned encf(float f){
    int b = __float_as_int(f);
    return (unsigned)(b ^ ((b >> 31) | 0x80000000));
}

// ---------------- K0: inv-norm of im1 patches + init encoded max ----------------
__global__ void __launch_bounds__(1024) norm_kernel(const float* __restrict__ im1){
    __shared__ float sA[PIX];        // channel-summed squares
    __shared__ float sH[HW*HP];      // horizontal box sums
    int b = blockIdx.x;
    int tid = threadIdx.x;
    const float* base = im1 + (size_t)b*NC*PIX;
    for (int p = tid; p < PIX; p += blockDim.x){
        float acc = 0.f;
        #pragma unroll 8
        for (int c = 0; c < NC; ++c){ float v = base[c*PIX + p]; acc += v*v; }
        sA[p] = acc;
    }
    __syncthreads();
    if (tid < HW){
        const float* row = &sA[tid*HW];
        for (int lx = 0; lx < HP; ++lx){
            float t = 0.f;
            #pragma unroll
            for (int j = 0; j < KS; ++j) t += row[lx+j];
            sH[tid*HP + lx] = t;
        }
    }
    __syncthreads();
    for (int t = tid; t < HP*HP; t += blockDim.x){
        int ly = t / HP, lx = t - ly*HP;
        float s = 0.f;
        #pragma unroll
        for (int i = 0; i < KS; ++i) s += sH[(ly+i)*HP + lx];
        float nrm = sqrtf(s);
        g_inv[b*HP*HP + t] = 1.0f / fmaxf(nrm, 1e-4f);
        g_enc[b*HP*HP + t] = 0u;   // < enc of any real float
    }
}

// ---------------- K1: displacement correlation + box sums + max ----------------
// grid: (4 dx-groups, 59 dy, 4 batch), 512 threads, dynamic smem
__global__ void __launch_bounds__(512, 1) corr_kernel(const float* __restrict__ im1,
                                                      const float* __restrict__ im2){
    extern __shared__ float smem[];
    float* s1   = smem;                 // [40*40]
    float* s2   = s1 + PIX;             // [40*112] zero-padded
    float* sq   = s2 + HW*PW;           // [NDX*1600]
    float* sinv = sq + NDX*PIX;         // [900]

    int tid  = threadIdx.x;
    int b    = blockIdx.z;
    int dy   = (int)blockIdx.y - 29;
    int dxlo = -29 + NDX*(int)blockIdx.x;

    // zero padded im2 buffer; load inv-norm
    for (int i = tid; i < (HW*PW)/4; i += 512)
        ((float4*)s2)[i] = make_float4(0.f,0.f,0.f,0.f);
    for (int i = tid; i < HP*HP; i += 512) sinv[i] = g_inv[b*HP*HP + i];

    int y0 = max(0, -dy), y1 = min(HW, HW - dy);
    int nrows = y1 - y0;
    int n4 = nrows * (HW/4);           // float4 count of one channel region (<=400)

    // per-thread strip: 4 consecutive x at row sy
    int sy = y0 + tid/10;
    int sx = (tid - (tid/10)*10) * 4;
    bool act = (tid < nrows*10);
    int i1 = sy*HW + sx;
    // dxlo mod 4 == 3 always -> fixed misalignment offset of 3
    int a0 = (sy+dy)*PW + POFF + sx + dxlo - 3;

    const float* g1 = im1 + (size_t)b*NC*PIX + y0*HW;
    const float* g2 = im2 + (size_t)b*NC*PIX + (y0+dy)*HW;

    // staging destinations
    int d1 = y0*HW + tid*4;
    int r2row = tid/10;
    int d2 = (y0+dy+r2row)*PW + POFF + (tid - r2row*10)*4;

    float q[NDX*4];
    #pragma unroll
    for (int i = 0; i < NDX*4; ++i) q[i] = 0.f;

    float4 f1 = make_float4(0.f,0.f,0.f,0.f), f2 = f1;
    if (tid < n4){
        f1 = ((const float4*)g1)[tid];
        f2 = ((const float4*)g2)[tid];
    }

    #pragma unroll 1
    for (int c = 0; c < NC; ++c){
        __syncthreads();                  // previous compute done / init done
        if (tid < n4){
            *(float4*)&s1[d1] = f1;
            *(float4*)&s2[d2] = f2;
        }
        __syncthreads();
        if (c+1 < NC && tid < n4){        // prefetch next channel (latency hidden)
            f1 = ((const float4*)(g1 + (c+1)*PIX))[tid];
            f2 = ((const float4*)(g2 + (c+1)*PIX))[tid];
        }
        if (act){
            float4 A = *(const float4*)&s1[i1];
            float w[24];
            #pragma unroll
            for (int k = 0; k < 6; ++k){
                float4 tv = *(const float4*)&s2[a0 + 4*k];
                w[4*k+0]=tv.x; w[4*k+1]=tv.y; w[4*k+2]=tv.z; w[4*k+3]=tv.w;
            }
            #pragma unroll
            for (int d = 0; d < NDX; ++d){
                q[d*4+0] += A.x * w[d+3];
                q[d*4+1] += A.y * w[d+4];
                q[d*4+2] += A.z * w[d+5];
                q[d*4+3] += A.w * w[d+6];
            }
        }
    }

    // dump accumulators to smem
    if (act){
        #pragma unroll
        for (int d = 0; d < NDX; ++d)
            *(float4*)&sq[d*PIX + i1] = make_float4(q[d*4+0],q[d*4+1],q[d*4+2],q[d*4+3]);
    }
    __syncthreads();

    // horizontal 11-sum (in place, cols 0..29)
    for (int t = tid; t < NDX*nrows; t += 512){
        int d = t / nrows;
        int y = y0 + (t - d*nrows);
        float* row = &sq[d*PIX + y*HW];
        float r[HW];
        #pragma unroll
        for (int k = 0; k < HW/4; ++k){
            float4 tv = *(const float4*)&row[4*k];
            r[4*k+0]=tv.x; r[4*k+1]=tv.y; r[4*k+2]=tv.z; r[4*k+3]=tv.w;
        }
        float s = 0.f;
        #pragma unroll
        for (int j = 0; j < KS; ++j) s += r[j];
        row[0] = s;
        #pragma unroll
        for (int lx = 1; lx < HP; ++lx){
            s += r[lx+KS-1] - r[lx-1];
            row[lx] = s;
        }
    }
    __syncthreads();

    // vertical 11-sum (in place, rows ly0..ly0+nly-1)
    int ly0 = max(0, -dy);
    int nly = min(HP, HP - dy) - ly0;
    for (int t = tid; t < NDX*HP; t += 512){
        int d = t / HP, lx = t - (t/HP)*HP;
        float* colp = &sq[d*PIX + lx];
        int cnt = nly + KS - 1;
        float v[HW];
        #pragma unroll
        for (int i = 0; i < HW; ++i) v[i] = (i < cnt) ? colp[(ly0+i)*HW] : 0.f;
        float s = 0.f;
        #pragma unroll
        for (int j = 0; j < KS; ++j) s += v[j];
        #pragma unroll
        for (int o = 0; o < HP; ++o){
            if (o < nly) colp[(ly0+o)*HW] = s;
            if (o+1 < HP) s += v[o+KS] - v[o];
        }
    }
    __syncthreads();

    // per-output max over this block's dx set, one atomicMax per p
    unsigned* eout = &g_enc[b*HP*HP];
    for (int t = tid; t < HP*HP; t += 512){
        int py = t / HP, px = t - (t/HP)*HP;
        int ly = py - dy;
        if (ly < 0 || ly >= HP) continue;
        float m = -3.0e38f;
        bool any = false;
        #pragma unroll
        for (int d = 0; d < NDX; ++d){
            int dx = dxlo + d;
            int lx = px - dx;
            if (dx <= 29 && lx >= 0 && lx < HP){
                float v = sq[d*PIX + ly*HW + lx] * sinv[ly*HP + lx];
                m = fmaxf(m, v);
                any = true;
            }
        }
        if (any) atomicMax(&eout[t], encf(m));
    }
}

// ---------------- K2: decode ----------------
__global__ void decode_kernel(float* __restrict__ out){
    int t = blockIdx.x*blockDim.x + threadIdx.x;
    if (t < OUTN){
        unsigned e = g_enc[t];
        int v = (e & 0x80000000u) ? (int)(e ^ 0x80000000u) : ~(int)e;
        out[t] = __int_as_float(v);
    }
}

extern "C" void kernel_launch(void* const* d_in, const int* in_sizes, int n_in,
                              void* d_out, int out_size){
    (void)in_sizes; (void)n_in; (void)out_size;
    const float* im1 = (const float*)d_in[0];
    const float* im2 = (const float*)d_in[1];

    const int smem_bytes = (PIX + HW*PW + NDX*PIX + HP*HP) * (int)sizeof(float);
    cudaFuncSetAttribute(corr_kernel, cudaFuncAttributeMaxDynamicSharedMemorySize, smem_bytes);

    norm_kernel<<<NB, 1024>>>(im1);
    corr_kernel<<<dim3(4, 59, NB), 512, smem_bytes>>>(im1, im2);
    decode_kernel<<<(OUTN + 255)/256, 256>>>((float*)d_out);
}